// round 4
// baseline (speedup 1.0000x reference)
#include <cuda_runtime.h>
#include <math.h>
#include <stdint.h>

// Problem constants
#define BSZ 4
#define TSEQ 1024
#define CDIM 1024
#define NHEAD 16
#define HDIM 64
#define FFDIM 4096
#define MTOK (BSZ * TSEQ)   // 4096 tokens

// ---------------------------------------------------------------------------
// Scratch buffers (allocation-free: __device__ globals)
// ---------------------------------------------------------------------------
__device__ float g_ln[MTOK * CDIM];
__device__ float g_q [MTOK * CDIM];
__device__ float g_k [MTOK * CDIM];
__device__ float g_v [MTOK * CDIM];
__device__ float g_a [MTOK * CDIM];
__device__ float g_x1[MTOK * CDIM];
__device__ float g_h [MTOK * FFDIM];

__device__ __forceinline__ uint32_t f2tf(float f) {
    uint32_t u;
    asm("cvt.rna.tf32.f32 %0, %1;" : "=r"(u) : "f"(f));
    return u;
}

// ---------------------------------------------------------------------------
// LayerNorm: one block per row of 1024, 256 threads, one float4 per thread
// ---------------------------------------------------------------------------
__global__ __launch_bounds__(256)
void ln_kernel(const float* __restrict__ x, const float* __restrict__ gamma,
               const float* __restrict__ beta, float* __restrict__ out)
{
    const int row = blockIdx.x;
    const int tid = threadIdx.x;
    const float4* xr = (const float4*)(x + (size_t)row * CDIM);
    float4 v = xr[tid];
    float s  = v.x + v.y + v.z + v.w;
    float sq = v.x * v.x + v.y * v.y + v.z * v.z + v.w * v.w;
    #pragma unroll
    for (int o = 16; o > 0; o >>= 1) {
        s  += __shfl_xor_sync(0xffffffffu, s,  o);
        sq += __shfl_xor_sync(0xffffffffu, sq, o);
    }
    __shared__ float ss[8], ssq[8];
    const int w = tid >> 5, lane = tid & 31;
    if (lane == 0) { ss[w] = s; ssq[w] = sq; }
    __syncthreads();
    float ts = 0.f, tsq = 0.f;
    #pragma unroll
    for (int i = 0; i < 8; i++) { ts += ss[i]; tsq += ssq[i]; }
    const float mean = ts * (1.0f / CDIM);
    const float var  = tsq * (1.0f / CDIM) - mean * mean;
    const float inv  = rsqrtf(var + 1e-5f);

    float4 gv = ((const float4*)gamma)[tid];
    float4 bv = ((const float4*)beta)[tid];
    float4 o4;
    o4.x = (v.x - mean) * inv * gv.x + bv.x;
    o4.y = (v.y - mean) * inv * gv.y + bv.y;
    o4.z = (v.z - mean) * inv * gv.z + bv.z;
    o4.w = (v.w - mean) * inv * gv.w + bv.w;
    ((float4*)(out + (size_t)row * CDIM))[tid] = o4;
}

// ---------------------------------------------------------------------------
// TF32 tensor-core GEMM core. 128x128x16 CTA tile, 256 threads = 8 warps
// (4 M x 2 N), warp tile 32x64 = 2x8 m16n8k8 atoms. Double-buffered smem,
// +8 padding -> conflict-free fragment loads.
// EPI: 0 = bias, 1 = bias + residual, 2 = bias + exact GELU
// ---------------------------------------------------------------------------
template <int EPI>
__device__ __forceinline__
void gemm_tc_body(const float* __restrict__ A, const float* __restrict__ W,
                  const float* __restrict__ bias, const float* __restrict__ res,
                  float* __restrict__ Cout, int Ndim, int Kdim,
                  int m0, int n0)
{
    __shared__ uint32_t As[2][16][136];   // [k][m] transposed
    __shared__ uint32_t Bs[2][16][136];   // [k][n]

    const int tid  = threadIdx.x;
    const int lane = tid & 31, warp = tid >> 5;
    const int wm = (warp & 3) * 32, wn = (warp >> 2) * 64;
    const int r = lane >> 2, c = lane & 3;

    const int ra = tid >> 2, ka = (tid & 3) * 4;
    const int kb = warp,     nb = lane * 4;

    const float* Ap0 = A + (size_t)(m0 + ra) * Kdim + ka;
    const float* Ap1 = Ap0 + (size_t)64 * Kdim;
    const float* Bp0 = W + (size_t)kb * Ndim + n0 + nb;
    const float* Bp1 = Bp0 + (size_t)8 * Ndim;

    float acc[2][8][4];
    #pragma unroll
    for (int mi = 0; mi < 2; mi++)
        #pragma unroll
        for (int ni = 0; ni < 8; ni++)
            #pragma unroll
            for (int q = 0; q < 4; q++) acc[mi][ni][q] = 0.f;

    float4 av0 = *(const float4*)Ap0;
    float4 av1 = *(const float4*)Ap1;
    float4 bv0 = *(const float4*)Bp0;
    float4 bv1 = *(const float4*)Bp1;

    // Stage buffer 0
    {
        As[0][ka+0][ra]    = f2tf(av0.x); As[0][ka+1][ra]    = f2tf(av0.y);
        As[0][ka+2][ra]    = f2tf(av0.z); As[0][ka+3][ra]    = f2tf(av0.w);
        As[0][ka+0][ra+64] = f2tf(av1.x); As[0][ka+1][ra+64] = f2tf(av1.y);
        As[0][ka+2][ra+64] = f2tf(av1.z); As[0][ka+3][ra+64] = f2tf(av1.w);
        uint4 t0 = make_uint4(f2tf(bv0.x), f2tf(bv0.y), f2tf(bv0.z), f2tf(bv0.w));
        uint4 t1 = make_uint4(f2tf(bv1.x), f2tf(bv1.y), f2tf(bv1.z), f2tf(bv1.w));
        *(uint4*)&Bs[0][kb][nb]     = t0;
        *(uint4*)&Bs[0][kb + 8][nb] = t1;
    }
    __syncthreads();

    int buf = 0;
    for (int k0 = 16; k0 <= Kdim; k0 += 16) {
        if (k0 < Kdim) {
            av0 = *(const float4*)(Ap0 + k0);
            av1 = *(const float4*)(Ap1 + k0);
            bv0 = *(const float4*)(Bp0 + (size_t)k0 * Ndim);
            bv1 = *(const float4*)(Bp1 + (size_t)k0 * Ndim);
        }

        #pragma unroll
        for (int s = 0; s < 2; s++) {
            const int kc = 8 * s + c;
            uint32_t af[2][4], bf[8][2];
            #pragma unroll
            for (int mi = 0; mi < 2; mi++) {
                af[mi][0] = As[buf][kc    ][wm + 16 * mi + r];
                af[mi][1] = As[buf][kc    ][wm + 16 * mi + r + 8];
                af[mi][2] = As[buf][kc + 4][wm + 16 * mi + r];
                af[mi][3] = As[buf][kc + 4][wm + 16 * mi + r + 8];
            }
            #pragma unroll
            for (int ni = 0; ni < 8; ni++) {
                bf[ni][0] = Bs[buf][kc    ][wn + 8 * ni + r];
                bf[ni][1] = Bs[buf][kc + 4][wn + 8 * ni + r];
            }
            #pragma unroll
            for (int mi = 0; mi < 2; mi++)
                #pragma unroll
                for (int ni = 0; ni < 8; ni++) {
                    asm volatile(
                        "mma.sync.aligned.m16n8k8.row.col.f32.tf32.tf32.f32 "
                        "{%0,%1,%2,%3}, {%4,%5,%6,%7}, {%8,%9}, {%0,%1,%2,%3};\n"
                        : "+f"(acc[mi][ni][0]), "+f"(acc[mi][ni][1]),
                          "+f"(acc[mi][ni][2]), "+f"(acc[mi][ni][3])
                        : "r"(af[mi][0]), "r"(af[mi][1]), "r"(af[mi][2]), "r"(af[mi][3]),
                          "r"(bf[ni][0]), "r"(bf[ni][1]));
                }
        }

        if (k0 < Kdim) {
            const int nbuf = buf ^ 1;
            As[nbuf][ka+0][ra]    = f2tf(av0.x); As[nbuf][ka+1][ra]    = f2tf(av0.y);
            As[nbuf][ka+2][ra]    = f2tf(av0.z); As[nbuf][ka+3][ra]    = f2tf(av0.w);
            As[nbuf][ka+0][ra+64] = f2tf(av1.x); As[nbuf][ka+1][ra+64] = f2tf(av1.y);
            As[nbuf][ka+2][ra+64] = f2tf(av1.z); As[nbuf][ka+3][ra+64] = f2tf(av1.w);
            uint4 t0 = make_uint4(f2tf(bv0.x), f2tf(bv0.y), f2tf(bv0.z), f2tf(bv0.w));
            uint4 t1 = make_uint4(f2tf(bv1.x), f2tf(bv1.y), f2tf(bv1.z), f2tf(bv1.w));
            *(uint4*)&Bs[nbuf][kb][nb]     = t0;
            *(uint4*)&Bs[nbuf][kb + 8][nb] = t1;
            __syncthreads();
            buf = nbuf;
        }
    }

    #pragma unroll
    for (int mi = 0; mi < 2; mi++) {
        #pragma unroll
        for (int half = 0; half < 2; half++) {
            const int row = m0 + wm + 16 * mi + r + 8 * half;
            #pragma unroll
            for (int ni = 0; ni < 8; ni++) {
                const int col = n0 + wn + 8 * ni + 2 * c;
                float v0 = acc[mi][ni][2 * half + 0] + bias[col];
                float v1 = acc[mi][ni][2 * half + 1] + bias[col + 1];
                if (EPI == 1) {
                    v0 += res[(size_t)row * Ndim + col];
                    v1 += res[(size_t)row * Ndim + col + 1];
                }
                if (EPI == 2) {
                    v0 = 0.5f * v0 * (1.0f + erff(v0 * 0.7071067811865475f));
                    v1 = 0.5f * v1 * (1.0f + erff(v1 * 0.7071067811865475f));
                }
                *(float2*)&Cout[(size_t)row * Ndim + col] = make_float2(v0, v1);
            }
        }
    }
}

template <int EPI>
__global__ __launch_bounds__(256)
void gemm_tc(const float* __restrict__ A, const float* __restrict__ W,
             const float* __restrict__ bias, const float* __restrict__ res,
             float* __restrict__ Cout, int Ndim, int Kdim)
{
    gemm_tc_body<EPI>(A, W, bias, res, Cout, Ndim, Kdim,
                      blockIdx.y * 128, blockIdx.x * 128);
}

// Fused QKV: blockIdx.z selects {W, bias, out}
struct QKVParams {
    const float *Wq, *Wk, *Wv, *bq, *bk, *bv;
    float *q, *k, *v;
};

__global__ __launch_bounds__(256)
void gemm_tc_qkv(const float* __restrict__ A, QKVParams p)
{
    const float* W; const float* b; float* o;
    if (blockIdx.z == 0)      { W = p.Wq; b = p.bq; o = p.q; }
    else if (blockIdx.z == 1) { W = p.Wk; b = p.bk; o = p.k; }
    else                      { W = p.Wv; b = p.bv; o = p.v; }
    gemm_tc_body<0>(A, W, b, nullptr, o, CDIM, CDIM,
                    blockIdx.y * 128, blockIdx.x * 128);
}

// ---------------------------------------------------------------------------
// Causal flash attention, fp32. grid (T/64, B*H), 256 threads.
// ---------------------------------------------------------------------------
__global__ __launch_bounds__(256)
void attn_kernel(const float* __restrict__ Q, const float* __restrict__ K,
                 const float* __restrict__ V, float* __restrict__ O)
{
    __shared__ float4 Qst[64][16];
    __shared__ float4 KVs[64][16];
    __shared__ float4 Pst[64][16];

    const int qt = blockIdx.x;
    const int b  = blockIdx.y >> 4;
    const int h  = blockIdx.y & 15;
    const int tid = threadIdx.x;
    const int tx = tid & 15, ty = tid >> 4;

    float* Qf  = (float*)Qst;
    float* KVf = (float*)KVs;

    const size_t qrow0 = (size_t)b * TSEQ + qt * 64;

    for (int i = tid; i < 4096; i += 256) {
        const int rr = i >> 6, cc = i & 63;
        const int grp = (rr >> 2) ^ (cc & 15);
        Qf[cc * 64 + grp * 4 + (rr & 3)] = Q[(qrow0 + rr) * CDIM + h * 64 + cc];
    }

    float m[4], l[4], acc[4][4];
    #pragma unroll
    for (int i = 0; i < 4; i++) {
        m[i] = -1e30f; l[i] = 0.f;
        #pragma unroll
        for (int j = 0; j < 4; j++) acc[i][j] = 0.f;
    }

    for (int kt = 0; kt <= qt; kt++) {
        const size_t krow0 = (size_t)b * TSEQ + kt * 64;
        __syncthreads();

        for (int i = tid; i < 4096; i += 256) {
            const int kr = i >> 6, cc = i & 63;
            const int grp = (kr >> 2) ^ (cc & 15);
            KVf[cc * 64 + grp * 4 + (kr & 3)] = K[(krow0 + kr) * CDIM + h * 64 + cc];
        }
        __syncthreads();

        float sv[4][4];
        #pragma unroll
        for (int i = 0; i < 4; i++)
            #pragma unroll
            for (int j = 0; j < 4; j++) sv[i][j] = 0.f;

        for (int k = 0; k < 64; k++) {
            const float4 q4 = Qst[k][ty ^ (k & 15)];
            const float4 k4 = KVs[k][tx ^ (k & 15)];
            const float qv[4] = {q4.x, q4.y, q4.z, q4.w};
            const float kv[4] = {k4.x, k4.y, k4.z, k4.w};
            #pragma unroll
            for (int i = 0; i < 4; i++)
                #pragma unroll
                for (int j = 0; j < 4; j++) sv[i][j] += qv[i] * kv[j];
        }

        const bool diag = (kt == qt);
        float alpha[4];
        #pragma unroll
        for (int i = 0; i < 4; i++) {
            const int ri = 4 * ty + i;
            float mt = -1e30f;
            #pragma unroll
            for (int j = 0; j < 4; j++) {
                float s = sv[i][j] * 0.125f;
                if (diag && (4 * tx + j) > ri) s = -1e30f;
                sv[i][j] = s;
                mt = fmaxf(mt, s);
            }
            #pragma unroll
            for (int o = 1; o < 16; o <<= 1)
                mt = fmaxf(mt, __shfl_xor_sync(0xffffffffu, mt, o));
            const float mnew = fmaxf(m[i], mt);
            alpha[i] = __expf(m[i] - mnew);
            float psum = 0.f;
            #pragma unroll
            for (int j = 0; j < 4; j++) {
                const float p = __expf(sv[i][j] - mnew);
                sv[i][j] = p;
                psum += p;
            }
            #pragma unroll
            for (int o = 1; o < 16; o <<= 1)
                psum += __shfl_xor_sync(0xffffffffu, psum, o);
            l[i] = l[i] * alpha[i] + psum;
            m[i] = mnew;
        }

        #pragma unroll
        for (int j = 0; j < 4; j++) {
            const int key = 4 * tx + j;
            float4 p4 = make_float4(sv[0][j], sv[1][j], sv[2][j], sv[3][j]);
            Pst[key][ty ^ (key & 15)] = p4;
        }
        __syncthreads();

        for (int i = tid; i < 4096; i += 256) {
            const int kr = i >> 6, cc = i & 63;
            KVf[kr * 64 + cc] = V[(krow0 + kr) * CDIM + h * 64 + cc];
        }
        __syncthreads();

        #pragma unroll
        for (int i = 0; i < 4; i++)
            #pragma unroll
            for (int j = 0; j < 4; j++) acc[i][j] *= alpha[i];

        for (int j = 0; j < 64; j++) {
            const float4 p4 = Pst[j][ty ^ (j & 15)];
            const float4 v4 = KVs[j][tx];
            const float pv[4] = {p4.x, p4.y, p4.z, p4.w};
            const float vv[4] = {v4.x, v4.y, v4.z, v4.w};
            #pragma unroll
            for (int i = 0; i < 4; i++)
                #pragma unroll
                for (int jj = 0; jj < 4; jj++) acc[i][jj] += pv[i] * vv[jj];
        }
    }

    #pragma unroll
    for (int i = 0; i < 4; i++) {
        const float linv = 1.0f / l[i];
        float4 o4 = make_float4(acc[i][0] * linv, acc[i][1] * linv,
                                acc[i][2] * linv, acc[i][3] * linv);
        *(float4*)&O[(qrow0 + 4 * ty + i) * CDIM + h * 64 + 4 * tx] = o4;
    }
}

// ---------------------------------------------------------------------------
// Launch
// ---------------------------------------------------------------------------
extern "C" void kernel_launch(void* const* d_in, const int* in_sizes, int n_in,
                              void* d_out, int out_size)
{
    const float* x   = (const float*)d_in[0];
    const float* Wq  = (const float*)d_in[1];
    const float* bq  = (const float*)d_in[2];
    const float* Wk  = (const float*)d_in[3];
    const float* bk  = (const float*)d_in[4];
    const float* Wv  = (const float*)d_in[5];
    const float* bv  = (const float*)d_in[6];
    const float* Wp  = (const float*)d_in[7];
    const float* bp  = (const float*)d_in[8];
    const float* W1  = (const float*)d_in[9];
    const float* b1  = (const float*)d_in[10];
    const float* W2  = (const float*)d_in[11];
    const float* b2  = (const float*)d_in[12];
    const float* g1  = (const float*)d_in[13];
    const float* be1 = (const float*)d_in[14];
    const float* g2  = (const float*)d_in[15];
    const float* be2 = (const float*)d_in[16];
    float* out = (float*)d_out;

    float *ln, *q, *k, *v, *a, *x1, *hbuf;
    cudaGetSymbolAddress((void**)&ln,   g_ln);
    cudaGetSymbolAddress((void**)&q,    g_q);
    cudaGetSymbolAddress((void**)&k,    g_k);
    cudaGetSymbolAddress((void**)&v,    g_v);
    cudaGetSymbolAddress((void**)&a,    g_a);
    cudaGetSymbolAddress((void**)&x1,   g_x1);
    cudaGetSymbolAddress((void**)&hbuf, g_h);

    const dim3 blk(256);

    ln_kernel<<<MTOK, blk>>>(x, g1, be1, ln);

    QKVParams qkv = {Wq, Wk, Wv, bq, bk, bv, q, k, v};
    gemm_tc_qkv<<<dim3(CDIM / 128, MTOK / 128, 3), blk>>>(ln, qkv);

    attn_kernel<<<dim3(TSEQ / 64, BSZ * NHEAD), blk>>>(q, k, v, a);

    gemm_tc<1><<<dim3(CDIM / 128, MTOK / 128), blk>>>(a, Wp, bp, x, x1, CDIM, CDIM);

    ln_kernel<<<MTOK, blk>>>(x1, g2, be2, ln);

    gemm_tc<2><<<dim3(FFDIM / 128, MTOK / 128), blk>>>(ln, W1, b1, nullptr, hbuf, FFDIM, CDIM);
    gemm_tc<1><<<dim3(CDIM / 128, MTOK / 128), blk>>>(hbuf, W2, b2, x1, out, CDIM, FFDIM);
}

// round 7
// speedup vs baseline: 1.7436x; 1.7436x over previous
#include <cuda_runtime.h>
#include <math.h>
#include <stdint.h>

// Problem constants
#define BSZ 4
#define TSEQ 1024
#define CDIM 1024
#define NHEAD 16
#define HDIM 64
#define FFDIM 4096
#define MTOK (BSZ * TSEQ)   // 4096 tokens

// ---------------------------------------------------------------------------
// Scratch buffers (allocation-free: __device__ globals)
// ---------------------------------------------------------------------------
__device__ float g_ln[MTOK * CDIM];
__device__ float g_q [MTOK * CDIM];
__device__ float g_k [MTOK * CDIM];
__device__ float g_v [MTOK * CDIM];
__device__ float g_a [MTOK * CDIM];
__device__ float g_x1[MTOK * CDIM];
__device__ float g_h [MTOK * FFDIM];

__device__ __forceinline__ uint32_t f2tf(float f) {
    uint32_t u;
    asm("cvt.rna.tf32.f32 %0, %1;" : "=r"(u) : "f"(f));
    return u;
}
// pack two floats to bf16x2: low half = lo, high half = hi
__device__ __forceinline__ uint32_t packbf(float lo, float hi) {
    uint32_t d;
    asm("cvt.rn.bf16x2.f32 %0, %1, %2;" : "=r"(d) : "f"(hi), "f"(lo));
    return d;
}

// ---------------------------------------------------------------------------
// LayerNorm: one block per row of 1024, 256 threads, one float4 per thread
// ---------------------------------------------------------------------------
__global__ __launch_bounds__(256)
void ln_kernel(const float* __restrict__ x, const float* __restrict__ gamma,
               const float* __restrict__ beta, float* __restrict__ out)
{
    const int row = blockIdx.x;
    const int tid = threadIdx.x;
    const float4* xr = (const float4*)(x + (size_t)row * CDIM);
    float4 v = xr[tid];
    float s  = v.x + v.y + v.z + v.w;
    float sq = v.x * v.x + v.y * v.y + v.z * v.z + v.w * v.w;
    #pragma unroll
    for (int o = 16; o > 0; o >>= 1) {
        s  += __shfl_xor_sync(0xffffffffu, s,  o);
        sq += __shfl_xor_sync(0xffffffffu, sq, o);
    }
    __shared__ float ss[8], ssq[8];
    const int w = tid >> 5, lane = tid & 31;
    if (lane == 0) { ss[w] = s; ssq[w] = sq; }
    __syncthreads();
    float ts = 0.f, tsq = 0.f;
    #pragma unroll
    for (int i = 0; i < 8; i++) { ts += ss[i]; tsq += ssq[i]; }
    const float mean = ts * (1.0f / CDIM);
    const float var  = tsq * (1.0f / CDIM) - mean * mean;
    const float inv  = rsqrtf(var + 1e-5f);

    float4 gv = ((const float4*)gamma)[tid];
    float4 bv = ((const float4*)beta)[tid];
    float4 o4;
    o4.x = (v.x - mean) * inv * gv.x + bv.x;
    o4.y = (v.y - mean) * inv * gv.y + bv.y;
    o4.z = (v.z - mean) * inv * gv.z + bv.z;
    o4.w = (v.w - mean) * inv * gv.w + bv.w;
    ((float4*)(out + (size_t)row * CDIM))[tid] = o4;
}

// ---------------------------------------------------------------------------
// BF16 tensor-core GEMM core. 128x128x16 CTA tile, 256 threads = 8 warps
// (4 M x 2 N), warp tile 32x64 = 2x8 m16n8k16 atoms. smem holds bf16x2
// k-pairs: As[kpair][m], Bs[kpair][n], stride 136 -> conflict-free fragment
// loads. Double-buffered.
// EPI: 0 = bias, 1 = bias + residual, 2 = bias + exact GELU
// ---------------------------------------------------------------------------
template <int EPI>
__device__ __forceinline__
void gemm_tc_body(const float* __restrict__ A, const float* __restrict__ W,
                  const float* __restrict__ bias, const float* __restrict__ res,
                  float* __restrict__ Cout, int Ndim, int Kdim,
                  int m0, int n0)
{
    __shared__ uint32_t As[2][8][136];   // [kpair][m], bf16x2 (k, k+1)
    __shared__ uint32_t Bs[2][8][136];   // [kpair][n], bf16x2 (k, k+1)

    const int tid  = threadIdx.x;
    const int lane = tid & 31, warp = tid >> 5;
    const int wm = (warp & 3) * 32, wn = (warp >> 2) * 64;
    const int r = lane >> 2, c = lane & 3;

    // A: thread loads rows ra, ra+64 at k-cols ka..ka+3 (one float4 each)
    const int ra = tid >> 2, ka = (tid & 3) * 4;
    const int kp = ka >> 1;               // k-pair index (0,2,4,6)
    // B: warp loads gmem k-rows 2*warp and 2*warp+1, n-cols nb..nb+3
    const int nb = lane * 4;

    const float* Ap0 = A + (size_t)(m0 + ra) * Kdim + ka;
    const float* Ap1 = Ap0 + (size_t)64 * Kdim;
    const float* Bp0 = W + (size_t)(2 * warp) * Ndim + n0 + nb;
    const float* Bp1 = Bp0 + Ndim;

    float acc[2][8][4];
    #pragma unroll
    for (int mi = 0; mi < 2; mi++)
        #pragma unroll
        for (int ni = 0; ni < 8; ni++)
            #pragma unroll
            for (int q = 0; q < 4; q++) acc[mi][ni][q] = 0.f;

    float4 av0 = *(const float4*)Ap0;
    float4 av1 = *(const float4*)Ap1;
    float4 bv0 = *(const float4*)Bp0;
    float4 bv1 = *(const float4*)Bp1;

    // Stage buffer 0
    {
        As[0][kp    ][ra]      = packbf(av0.x, av0.y);
        As[0][kp + 1][ra]      = packbf(av0.z, av0.w);
        As[0][kp    ][ra + 64] = packbf(av1.x, av1.y);
        As[0][kp + 1][ra + 64] = packbf(av1.z, av1.w);
        uint4 t = make_uint4(packbf(bv0.x, bv1.x), packbf(bv0.y, bv1.y),
                             packbf(bv0.z, bv1.z), packbf(bv0.w, bv1.w));
        *(uint4*)&Bs[0][warp][nb] = t;
    }
    __syncthreads();

    int buf = 0;
    for (int k0 = 16; k0 <= Kdim; k0 += 16) {
        if (k0 < Kdim) {
            av0 = *(const float4*)(Ap0 + k0);
            av1 = *(const float4*)(Ap1 + k0);
            bv0 = *(const float4*)(Bp0 + (size_t)k0 * Ndim);
            bv1 = *(const float4*)(Bp1 + (size_t)k0 * Ndim);
        }

        // One m16n8k16 step covers the whole 16-k tile
        {
            uint32_t af[2][4], bf[8][2];
            #pragma unroll
            for (int mi = 0; mi < 2; mi++) {
                af[mi][0] = As[buf][c    ][wm + 16 * mi + r];
                af[mi][1] = As[buf][c    ][wm + 16 * mi + r + 8];
                af[mi][2] = As[buf][c + 4][wm + 16 * mi + r];
                af[mi][3] = As[buf][c + 4][wm + 16 * mi + r + 8];
            }
            #pragma unroll
            for (int ni = 0; ni < 8; ni++) {
                bf[ni][0] = Bs[buf][c    ][wn + 8 * ni + r];
                bf[ni][1] = Bs[buf][c + 4][wn + 8 * ni + r];
            }
            #pragma unroll
            for (int mi = 0; mi < 2; mi++)
                #pragma unroll
                for (int ni = 0; ni < 8; ni++) {
                    asm volatile(
                        "mma.sync.aligned.m16n8k16.row.col.f32.bf16.bf16.f32 "
                        "{%0,%1,%2,%3}, {%4,%5,%6,%7}, {%8,%9}, {%0,%1,%2,%3};\n"
                        : "+f"(acc[mi][ni][0]), "+f"(acc[mi][ni][1]),
                          "+f"(acc[mi][ni][2]), "+f"(acc[mi][ni][3])
                        : "r"(af[mi][0]), "r"(af[mi][1]), "r"(af[mi][2]), "r"(af[mi][3]),
                          "r"(bf[ni][0]), "r"(bf[ni][1]));
                }
        }

        if (k0 < Kdim) {
            const int nbuf = buf ^ 1;
            As[nbuf][kp    ][ra]      = packbf(av0.x, av0.y);
            As[nbuf][kp + 1][ra]      = packbf(av0.z, av0.w);
            As[nbuf][kp    ][ra + 64] = packbf(av1.x, av1.y);
            As[nbuf][kp + 1][ra + 64] = packbf(av1.z, av1.w);
            uint4 t = make_uint4(packbf(bv0.x, bv1.x), packbf(bv0.y, bv1.y),
                                 packbf(bv0.z, bv1.z), packbf(bv0.w, bv1.w));
            *(uint4*)&Bs[nbuf][warp][nb] = t;
            __syncthreads();
            buf = nbuf;
        }
    }

    #pragma unroll
    for (int mi = 0; mi < 2; mi++) {
        #pragma unroll
        for (int half = 0; half < 2; half++) {
            const int row = m0 + wm + 16 * mi + r + 8 * half;
            #pragma unroll
            for (int ni = 0; ni < 8; ni++) {
                const int col = n0 + wn + 8 * ni + 2 * c;
                float v0 = acc[mi][ni][2 * half + 0] + bias[col];
                float v1 = acc[mi][ni][2 * half + 1] + bias[col + 1];
                if (EPI == 1) {
                    v0 += res[(size_t)row * Ndim + col];
                    v1 += res[(size_t)row * Ndim + col + 1];
                }
                if (EPI == 2) {
                    v0 = 0.5f * v0 * (1.0f + erff(v0 * 0.7071067811865475f));
                    v1 = 0.5f * v1 * (1.0f + erff(v1 * 0.7071067811865475f));
                }
                *(float2*)&Cout[(size_t)row * Ndim + col] = make_float2(v0, v1);
            }
        }
    }
}

template <int EPI>
__global__ __launch_bounds__(256)
void gemm_tc(const float* __restrict__ A, const float* __restrict__ W,
             const float* __restrict__ bias, const float* __restrict__ res,
             float* __restrict__ Cout, int Ndim, int Kdim)
{
    gemm_tc_body<EPI>(A, W, bias, res, Cout, Ndim, Kdim,
                      blockIdx.y * 128, blockIdx.x * 128);
}

// Fused QKV: blockIdx.z selects {W, bias, out}
struct QKVParams {
    const float *Wq, *Wk, *Wv, *bq, *bk, *bv;
    float *q, *k, *v;
};

__global__ __launch_bounds__(256)
void gemm_tc_qkv(const float* __restrict__ A, QKVParams p)
{
    const float* W; const float* b; float* o;
    if (blockIdx.z == 0)      { W = p.Wq; b = p.bq; o = p.q; }
    else if (blockIdx.z == 1) { W = p.Wk; b = p.bk; o = p.k; }
    else                      { W = p.Wv; b = p.bv; o = p.v; }
    gemm_tc_body<0>(A, W, b, nullptr, o, CDIM, CDIM,
                    blockIdx.y * 128, blockIdx.x * 128);
}

// ---------------------------------------------------------------------------
// Causal flash attention with TF32 tensor cores.
// grid (T/64, B*H), 128 threads = 4 warps; warp w owns q-rows 16w..16w+15.
// Q pre-scaled by 1/8 (exact), held as register A-fragments.
// smem: KtPs (K^T[d][key], later aliased as P[q][key]) + Vs (V[key][d]),
// both tf32 bits, stride 68 -> conflict-free fragment loads.
// ---------------------------------------------------------------------------
__global__ __launch_bounds__(128)
void attn_tc(const float* __restrict__ Q, const float* __restrict__ K,
             const float* __restrict__ V, float* __restrict__ O)
{
    __shared__ uint32_t KtPs[64][68];
    __shared__ uint32_t Vs[64][68];

    const int qt = blockIdx.x;
    const int b  = blockIdx.y >> 4;
    const int h  = blockIdx.y & 15;
    const int tid = threadIdx.x;
    const int w = tid >> 5, lane = tid & 31;
    const int r = lane >> 2, c = lane & 3;
    const size_t qrow0 = (size_t)b * TSEQ + qt * 64;

    // Stage Q (pre-scaled) into Vs as raw float bits, then build A-fragments
    for (int i = tid; i < 4096; i += 128) {
        const int rr = i >> 6, cc = i & 63;
        Vs[rr][cc] = __float_as_uint(Q[(qrow0 + rr) * CDIM + h * 64 + cc] * 0.125f);
    }
    __syncthreads();

    uint32_t qf[8][4];
    #pragma unroll
    for (int s = 0; s < 8; s++) {
        qf[s][0] = f2tf(__uint_as_float(Vs[16 * w + r    ][8 * s + c    ]));
        qf[s][1] = f2tf(__uint_as_float(Vs[16 * w + r + 8][8 * s + c    ]));
        qf[s][2] = f2tf(__uint_as_float(Vs[16 * w + r    ][8 * s + c + 4]));
        qf[s][3] = f2tf(__uint_as_float(Vs[16 * w + r + 8][8 * s + c + 4]));
    }

    float of[8][4];
    #pragma unroll
    for (int ni = 0; ni < 8; ni++)
        #pragma unroll
        for (int q = 0; q < 4; q++) of[ni][q] = 0.f;
    float m2[2] = {-1e30f, -1e30f};
    float l2[2] = {0.f, 0.f};

    for (int kt = 0; kt <= qt; kt++) {
        const size_t kr0 = (size_t)b * TSEQ + kt * 64;
        __syncthreads();   // prior PV reads (and qf staging reads) complete

        for (int i = tid; i < 4096; i += 128) {
            const int rr = i >> 6, cc = i & 63;   // rr = key, cc = d
            const size_t g = (kr0 + rr) * CDIM + h * 64 + cc;
            KtPs[cc][rr] = f2tf(K[g]);
            Vs[rr][cc]   = f2tf(V[g]);
        }
        __syncthreads();

        // S = Q K^T (scaled): per warp m16 x n64 x k64
        float sv[8][4];
        #pragma unroll
        for (int ni = 0; ni < 8; ni++)
            #pragma unroll
            for (int q = 0; q < 4; q++) sv[ni][q] = 0.f;

        #pragma unroll
        for (int s = 0; s < 8; s++) {
            uint32_t kb[8][2];
            #pragma unroll
            for (int ni = 0; ni < 8; ni++) {
                kb[ni][0] = KtPs[8 * s + c    ][8 * ni + r];
                kb[ni][1] = KtPs[8 * s + c + 4][8 * ni + r];
            }
            #pragma unroll
            for (int ni = 0; ni < 8; ni++) {
                asm volatile(
                    "mma.sync.aligned.m16n8k8.row.col.f32.tf32.tf32.f32 "
                    "{%0,%1,%2,%3}, {%4,%5,%6,%7}, {%8,%9}, {%0,%1,%2,%3};\n"
                    : "+f"(sv[ni][0]), "+f"(sv[ni][1]), "+f"(sv[ni][2]), "+f"(sv[ni][3])
                    : "r"(qf[s][0]), "r"(qf[s][1]), "r"(qf[s][2]), "r"(qf[s][3]),
                      "r"(kb[ni][0]), "r"(kb[ni][1]));
            }
        }

        // causal mask on diagonal tile
        if (kt == qt) {
            #pragma unroll
            for (int ni = 0; ni < 8; ni++)
                #pragma unroll
                for (int q = 0; q < 4; q++) {
                    const int col  = 8 * ni + 2 * c + (q & 1);
                    const int rowl = 16 * w + r + 8 * (q >> 1);
                    if (col > rowl) sv[ni][q] = -1e30f;
                }
        }

        // online softmax (two row-halves per thread)
        float alpha[2];
        #pragma unroll
        for (int hh = 0; hh < 2; hh++) {
            float mt = -1e30f;
            #pragma unroll
            for (int ni = 0; ni < 8; ni++) {
                mt = fmaxf(mt, sv[ni][2 * hh]);
                mt = fmaxf(mt, sv[ni][2 * hh + 1]);
            }
            mt = fmaxf(mt, __shfl_xor_sync(0xffffffffu, mt, 1));
            mt = fmaxf(mt, __shfl_xor_sync(0xffffffffu, mt, 2));
            const float mnew = fmaxf(m2[hh], mt);
            alpha[hh] = __expf(m2[hh] - mnew);
            float ls = 0.f;
            #pragma unroll
            for (int ni = 0; ni < 8; ni++) {
                float p0 = __expf(sv[ni][2 * hh]     - mnew);
                float p1 = __expf(sv[ni][2 * hh + 1] - mnew);
                sv[ni][2 * hh] = p0; sv[ni][2 * hh + 1] = p1;
                ls += p0 + p1;
            }
            ls += __shfl_xor_sync(0xffffffffu, ls, 1);
            ls += __shfl_xor_sync(0xffffffffu, ls, 2);
            l2[hh] = l2[hh] * alpha[hh] + ls;
            m2[hh] = mnew;
        }
        #pragma unroll
        for (int ni = 0; ni < 8; ni++) {
            of[ni][0] *= alpha[0]; of[ni][1] *= alpha[0];
            of[ni][2] *= alpha[1]; of[ni][3] *= alpha[1];
        }

        __syncthreads();   // all warps done reading Kt -> reuse as Ps
        #pragma unroll
        for (int ni = 0; ni < 8; ni++) {
            const int col = 8 * ni + 2 * c;
            KtPs[16 * w + r    ][col]     = f2tf(sv[ni][0]);
            KtPs[16 * w + r    ][col + 1] = f2tf(sv[ni][1]);
            KtPs[16 * w + r + 8][col]     = f2tf(sv[ni][2]);
            KtPs[16 * w + r + 8][col + 1] = f2tf(sv[ni][3]);
        }
        __syncthreads();

        // O += P V: per warp m16 x n64 x k64
        #pragma unroll
        for (int s = 0; s < 8; s++) {
            uint32_t pa[4];
            pa[0] = KtPs[16 * w + r    ][8 * s + c    ];
            pa[1] = KtPs[16 * w + r + 8][8 * s + c    ];
            pa[2] = KtPs[16 * w + r    ][8 * s + c + 4];
            pa[3] = KtPs[16 * w + r + 8][8 * s + c + 4];
            #pragma unroll
            for (int ni = 0; ni < 8; ni++) {
                uint32_t vb0 = Vs[8 * s + c    ][8 * ni + r];
                uint32_t vb1 = Vs[8 * s + c + 4][8 * ni + r];
                asm volatile(
                    "mma.sync.aligned.m16n8k8.row.col.f32.tf32.tf32.f32 "
                    "{%0,%1,%2,%3}, {%4,%5,%6,%7}, {%8,%9}, {%0,%1,%2,%3};\n"
                    : "+f"(of[ni][0]), "+f"(of[ni][1]), "+f"(of[ni][2]), "+f"(of[ni][3])
                    : "r"(pa[0]), "r"(pa[1]), "r"(pa[2]), "r"(pa[3]),
                      "r"(vb0), "r"(vb1));
            }
        }
    }

    const float inv0 = 1.0f / l2[0];
    const float inv1 = 1.0f / l2[1];
    #pragma unroll
    for (int ni = 0; ni < 8; ni++) {
        const size_t row = qrow0 + 16 * w + r;
        const int col = h * 64 + 8 * ni + 2 * c;
        *(float2*)&O[row * CDIM + col] =
            make_float2(of[ni][0] * inv0, of[ni][1] * inv0);
        *(float2*)&O[(row + 8) * CDIM + col] =
            make_float2(of[ni][2] * inv1, of[ni][3] * inv1);
    }
}

// ---------------------------------------------------------------------------
// Launch
// ---------------------------------------------------------------------------
extern "C" void kernel_launch(void* const* d_in, const int* in_sizes, int n_in,
                              void* d_out, int out_size)
{
    const float* x   = (const float*)d_in[0];
    const float* Wq  = (const float*)d_in[1];
    const float* bq  = (const float*)d_in[2];
    const float* Wk  = (const float*)d_in[3];
    const float* bk  = (const float*)d_in[4];
    const float* Wv  = (const float*)d_in[5];
    const float* bv  = (const float*)d_in[6];
    const float* Wp  = (const float*)d_in[7];
    const float* bp  = (const float*)d_in[8];
    const float* W1  = (const float*)d_in[9];
    const float* b1  = (const float*)d_in[10];
    const float* W2  = (const float*)d_in[11];
    const float* b2  = (const float*)d_in[12];
    const float* g1  = (const float*)d_in[13];
    const float* be1 = (const float*)d_in[14];
    const float* g2  = (const float*)d_in[15];
    const float* be2 = (const float*)d_in[16];
    float* out = (float*)d_out;

    float *ln, *q, *k, *v, *a, *x1, *hbuf;
    cudaGetSymbolAddress((void**)&ln,   g_ln);
    cudaGetSymbolAddress((void**)&q,    g_q);
    cudaGetSymbolAddress((void**)&k,    g_k);
    cudaGetSymbolAddress((void**)&v,    g_v);
    cudaGetSymbolAddress((void**)&a,    g_a);
    cudaGetSymbolAddress((void**)&x1,   g_x1);
    cudaGetSymbolAddress((void**)&hbuf, g_h);

    const dim3 blk(256);

    ln_kernel<<<MTOK, blk>>>(x, g1, be1, ln);

    QKVParams qkv = {Wq, Wk, Wv, bq, bk, bv, q, k, v};
    gemm_tc_qkv<<<dim3(CDIM / 128, MTOK / 128, 3), blk>>>(ln, qkv);

    attn_tc<<<dim3(TSEQ / 64, BSZ * NHEAD), 128>>>(q, k, v, a);

    gemm_tc<1><<<dim3(CDIM / 128, MTOK / 128), blk>>>(a, Wp, bp, x, x1, CDIM, CDIM);

    ln_kernel<<<MTOK, blk>>>(x1, g2, be2, ln);

    gemm_tc<2><<<dim3(FFDIM / 128, MTOK / 128), blk>>>(ln, W1, b1, nullptr, hbuf, FFDIM, CDIM);
    gemm_tc<1><<<dim3(CDIM / 128, MTOK / 128), blk>>>(hbuf, W2, b2, x1, out, CDIM, FFDIM);
}